// round 1
// baseline (speedup 1.0000x reference)
#include <cuda_runtime.h>
#include <math.h>

// ---------------- problem constants ----------------
#define BB   8
#define CC   256
#define LL   512
#define NG   32      // groups
#define CPG  8       // channels per group
#define NH   8       // heads
#define DH   32      // head dim
#define EE   1024    // experts
#define HIDD 32
#define CAPP 4
#define NTOK 256     // tokens per batch for MoE (=C)
#define DTOK 512     // token dim for MoE (=L)

// ---------------- scratch (device globals; allocation-free) ----------------
__device__ float g_x1[BB*CC*LL];
__device__ float g_h [BB*CC*LL];
__device__ float g_r [BB*CC*LL];
__device__ float g_xa[BB*CC*LL];
__device__ float g_xT[BB*LL*CC];
__device__ float g_t [BB*LL*3*CC];
__device__ float g_q [BB*NH*LL*DH];
__device__ float g_k [BB*NH*LL*DH];
__device__ float g_v [BB*NH*LL*DH];
__device__ float g_s [(size_t)BB*NH*LL*LL];
__device__ float g_oc[BB*LL*CC];
__device__ float g_lc[BB*LL*CC];
__device__ float g_xb[BB*CC*LL];
__device__ float g_xm[BB*CC*LL];
__device__ float g_logits[BB*NTOK*EE];
__device__ float g_raw  [BB*NTOK*EE];
__device__ float g_gate1[BB*NTOK];
__device__ float g_gate2[BB*NTOK];
__device__ int   g_i1[BB*NTOK];
__device__ int   g_i2[BB*NTOK];
__device__ float g_rawsum[BB*EE];
__device__ float g_cnt1 [BB*EE];
__device__ int   g_slot_tok [BB*EE*CAPP];
__device__ float g_slot_gate[BB*EE*CAPP];
__device__ float g_moeout[BB*CC*LL];
__device__ float g_yfull[(size_t)BB*2*CC*LL];

__device__ __forceinline__ float gelu_exact(float v) {
    return 0.5f * v * (1.0f + erff(v * 0.7071067811865476f));
}

// ---------------- GroupNorm (+optional emb add) + GELU, fused ----------------
// grid: BB*NG blocks (one per (b,group)); block 256 threads; group data is contiguous 4096 floats
__global__ void gn_gelu_kernel(const float* __restrict__ xin, const float* __restrict__ emb,
                               const float* __restrict__ scale, const float* __restrict__ bias,
                               float* __restrict__ x1_out, float* __restrict__ h_out) {
    int b = blockIdx.x >> 5;
    int g = blockIdx.x & 31;
    size_t base = ((size_t)b * CC + g * CPG) * LL;
    __shared__ float vals[CPG * LL];
    __shared__ float red[256];
    int tid = threadIdx.x;
    float s = 0.f, s2 = 0.f;
#pragma unroll
    for (int i = 0; i < 16; i++) {
        int j = tid + i * 256;
        float v = xin[base + j];
        if (emb) v += emb[base + j];
        vals[j] = v;
        s += v;
        s2 = fmaf(v, v, s2);
    }
    red[tid] = s; __syncthreads();
    for (int o = 128; o > 0; o >>= 1) { if (tid < o) red[tid] += red[tid + o]; __syncthreads(); }
    float mean = red[0] * (1.f / 4096.f);
    __syncthreads();
    red[tid] = s2; __syncthreads();
    for (int o = 128; o > 0; o >>= 1) { if (tid < o) red[tid] += red[tid + o]; __syncthreads(); }
    float var = red[0] * (1.f / 4096.f) - mean * mean;
    float rsig = rsqrtf(var + 1e-5f);
#pragma unroll
    for (int i = 0; i < 16; i++) {
        int j = tid + i * 256;
        int c = g * CPG + (j >> 9);
        float v = vals[j];
        if (x1_out) x1_out[base + j] = v;
        float nn = (v - mean) * rsig * scale[c] + bias[c];
        h_out[base + j] = gelu_exact(nn);
    }
}

// ---------------- conv1d k=3 pad=1 as implicit GEMM ----------------
// out[b,o,l] = bias[o] + sum_{i,t} W[o, i*3+t] * X[b,i,l+t-1]  (+ optional residual)
// M = OC (tile 128), N = BB*LL = 4096 (tile 64), K = CC*3 = 768 (tile 16)
__global__ void conv3_kernel(const float* __restrict__ W, const float* __restrict__ X,
                             const float* __restrict__ bias, const float* __restrict__ res,
                             float* __restrict__ Y, int OC) {
    const int Kdim = CC * 3;
    __shared__ float As[16][128];
    __shared__ float Bs[16][64];
    int tid = threadIdx.x;
    int m0 = blockIdx.y * 128;
    int n0 = blockIdx.x * 64;
    int tx = tid & 15, ty = tid >> 4;
    float acc[8][4] = {};
    for (int k0 = 0; k0 < Kdim; k0 += 16) {
#pragma unroll
        for (int i = 0; i < 8; i++) {
            int idx = tid + i * 256;
            int m = idx >> 4, k = idx & 15;
            As[k][m] = W[(size_t)(m0 + m) * Kdim + k0 + k];
        }
#pragma unroll
        for (int i = 0; i < 4; i++) {
            int idx = tid + i * 256;
            int k = idx >> 6, n = idx & 63;
            int kg = k0 + k;
            int ic = kg / 3, t = kg - ic * 3;
            int nn = n0 + n;
            int b = nn >> 9, l = nn & 511;
            int ll = l + t - 1;
            Bs[k][n] = ((unsigned)ll < (unsigned)LL) ? X[((size_t)(b * CC + ic) << 9) + ll] : 0.f;
        }
        __syncthreads();
#pragma unroll
        for (int kk = 0; kk < 16; kk++) {
            float a[8], bq[4];
#pragma unroll
            for (int i = 0; i < 8; i++) a[i] = As[kk][ty * 8 + i];
#pragma unroll
            for (int j = 0; j < 4; j++) bq[j] = Bs[kk][tx * 4 + j];
#pragma unroll
            for (int i = 0; i < 8; i++)
#pragma unroll
                for (int j = 0; j < 4; j++) acc[i][j] = fmaf(a[i], bq[j], acc[i][j]);
        }
        __syncthreads();
    }
#pragma unroll
    for (int i = 0; i < 8; i++) {
        int o = m0 + ty * 8 + i;
#pragma unroll
        for (int j = 0; j < 4; j++) {
            int nn = n0 + tx * 4 + j;
            int b = nn >> 9, l = nn & 511;
            size_t oi = ((size_t)(b * OC + o) << 9) + l;
            float v = acc[i][j] + bias[o];
            if (res) v += res[oi];
            Y[oi] = v;
        }
    }
}

// ---------------- generic SGEMM C = A(MxK) @ B(KxN) (+bias) ----------------
__global__ void sgemm_kernel(const float* __restrict__ A, const float* __restrict__ Bm,
                             const float* __restrict__ bias, float* __restrict__ Cm,
                             int M, int N, int K) {
    __shared__ float As[16][128];
    __shared__ float Bs[16][64];
    int tid = threadIdx.x;
    int m0 = blockIdx.y * 128;
    int n0 = blockIdx.x * 64;
    int tx = tid & 15, ty = tid >> 4;
    float acc[8][4] = {};
    for (int k0 = 0; k0 < K; k0 += 16) {
#pragma unroll
        for (int i = 0; i < 8; i++) {
            int idx = tid + i * 256;
            int m = idx >> 4, k = idx & 15;
            As[k][m] = A[(size_t)(m0 + m) * K + k0 + k];
        }
#pragma unroll
        for (int i = 0; i < 4; i++) {
            int idx = tid + i * 256;
            int k = idx >> 6, n = idx & 63;
            Bs[k][n] = Bm[(size_t)(k0 + k) * N + n0 + n];
        }
        __syncthreads();
#pragma unroll
        for (int kk = 0; kk < 16; kk++) {
            float a[8], bq[4];
#pragma unroll
            for (int i = 0; i < 8; i++) a[i] = As[kk][ty * 8 + i];
#pragma unroll
            for (int j = 0; j < 4; j++) bq[j] = Bs[kk][tx * 4 + j];
#pragma unroll
            for (int i = 0; i < 8; i++)
#pragma unroll
                for (int j = 0; j < 4; j++) acc[i][j] = fmaf(a[i], bq[j], acc[i][j]);
        }
        __syncthreads();
    }
#pragma unroll
    for (int i = 0; i < 8; i++) {
        int m = m0 + ty * 8 + i;
#pragma unroll
        for (int j = 0; j < 4; j++) {
            int n = n0 + tx * 4 + j;
            float v = acc[i][j];
            if (bias) v += bias[n];
            Cm[(size_t)m * N + n] = v;
        }
    }
}

// ---------------- batched transpose: out[b,s,r] = in[b,r,s] ----------------
__global__ void transpose_kernel(const float* __restrict__ in, float* __restrict__ out, int R, int S) {
    __shared__ float tile[32][33];
    int b = blockIdx.z;
    int s0 = blockIdx.x * 32, r0 = blockIdx.y * 32;
    int x = threadIdx.x, y = threadIdx.y;
#pragma unroll
    for (int i = 0; i < 32; i += 8) {
        int r = r0 + y + i, s = s0 + x;
        tile[y + i][x] = in[((size_t)b * R + r) * S + s];
    }
    __syncthreads();
#pragma unroll
    for (int i = 0; i < 32; i += 8) {
        int s = s0 + y + i, r = r0 + x;
        out[((size_t)b * S + s) * R + r] = tile[x][y + i];
    }
}

// ---------------- qkv split: t(B,L,768) -> Q,K,V (B,H,L,DH) ----------------
__global__ void qkv_split_kernel(const float* __restrict__ t, float* __restrict__ Q,
                                 float* __restrict__ K, float* __restrict__ V) {
    int idx = blockIdx.x * 256 + threadIdx.x;     // 1M threads
    int d = idx & 31;
    int l = (idx >> 5) & 511;
    int h = (idx >> 14) & 7;
    int b = idx >> 17;
    size_t base = ((size_t)(b * LL + l)) * 768 + (size_t)(d * NH + h) * 3;
    int o = ((b * NH + h) * LL + l) * DH + d;
    Q[o] = t[base];
    K[o] = t[base + 1];
    V[o] = t[base + 2];
}

// ---------------- scores S[bh,q,k] = Q.K / sqrt(DH) ----------------
__global__ void attn_score_kernel(const float* __restrict__ Q, const float* __restrict__ K,
                                  float* __restrict__ S) {
    int bh = blockIdx.z;
    int q0 = blockIdx.y * 64, k0 = blockIdx.x * 64;
    __shared__ float Qs[64][33];
    __shared__ float Ks[64][33];
    int tid = threadIdx.x;
#pragma unroll
    for (int i = 0; i < 8; i++) {
        int idx = tid + i * 256;
        int r = idx >> 5, d = idx & 31;
        Qs[r][d] = Q[((size_t)(bh << 9) + q0 + r) * 32 + d];
        Ks[r][d] = K[((size_t)(bh << 9) + k0 + r) * 32 + d];
    }
    __syncthreads();
    int tx = tid & 15, ty = tid >> 4;
    float acc[4][4] = {};
#pragma unroll
    for (int kk = 0; kk < 32; kk++) {
        float a[4], bq[4];
#pragma unroll
        for (int i = 0; i < 4; i++) a[i] = Qs[ty * 4 + i][kk];
#pragma unroll
        for (int j = 0; j < 4; j++) bq[j] = Ks[tx * 4 + j][kk];
#pragma unroll
        for (int i = 0; i < 4; i++)
#pragma unroll
            for (int j = 0; j < 4; j++) acc[i][j] = fmaf(a[i], bq[j], acc[i][j]);
    }
    const float sc = 0.17677669529663687f;  // 1/sqrt(32)
    size_t base = (size_t)bh << 18;
#pragma unroll
    for (int i = 0; i < 4; i++)
#pragma unroll
        for (int j = 0; j < 4; j++)
            S[base + (size_t)(q0 + ty * 4 + i) * 512 + k0 + tx * 4 + j] = acc[i][j] * sc;
}

// ---------------- softmax over rows of 512 ----------------
__global__ void softmax512_kernel(float* __restrict__ S) {
    size_t row = blockIdx.x;
    float* p = S + row * 512;
    int tid = threadIdx.x;       // 128
    __shared__ float red[128];
    float v[4];
#pragma unroll
    for (int i = 0; i < 4; i++) v[i] = p[tid + i * 128];
    float m = fmaxf(fmaxf(v[0], v[1]), fmaxf(v[2], v[3]));
    red[tid] = m; __syncthreads();
    for (int o = 64; o > 0; o >>= 1) { if (tid < o) red[tid] = fmaxf(red[tid], red[tid + o]); __syncthreads(); }
    m = red[0]; __syncthreads();
    float s = 0.f;
#pragma unroll
    for (int i = 0; i < 4; i++) { v[i] = expf(v[i] - m); s += v[i]; }
    red[tid] = s; __syncthreads();
    for (int o = 64; o > 0; o >>= 1) { if (tid < o) red[tid] += red[tid + o]; __syncthreads(); }
    float inv = 1.f / red[0];
#pragma unroll
    for (int i = 0; i < 4; i++) p[tid + i * 128] = v[i] * inv;
}

// ---------------- O = P @ V, write as oc[b,l, d*H + h] ----------------
__global__ void attn_av_kernel(const float* __restrict__ S, const float* __restrict__ V,
                               float* __restrict__ OCb) {
    int bh = blockIdx.y;
    int q0 = blockIdx.x * 64;
    int b = bh >> 3, h = bh & 7;
    __shared__ float Ps[64][65];
    __shared__ float Vs[64][32];
    int tid = threadIdx.x;
    int d = tid & 31, qg = tid >> 5;
    float acc[8] = {};
    for (int k0 = 0; k0 < 512; k0 += 64) {
#pragma unroll
        for (int i = 0; i < 16; i++) {
            int idx = tid + i * 256;
            int r = idx >> 6, c = idx & 63;
            Ps[r][c] = S[((size_t)bh << 18) + (size_t)(q0 + r) * 512 + k0 + c];
        }
#pragma unroll
        for (int i = 0; i < 8; i++) {
            int idx = tid + i * 256;
            int r = idx >> 5, c = idx & 31;
            Vs[r][c] = V[((size_t)(bh << 9) + k0 + r) * 32 + c];
        }
        __syncthreads();
#pragma unroll
        for (int kk = 0; kk < 64; kk++) {
            float vv = Vs[kk][d];
#pragma unroll
            for (int j = 0; j < 8; j++) acc[j] = fmaf(Ps[qg + j * 8][kk], vv, acc[j]);
        }
        __syncthreads();
    }
#pragma unroll
    for (int j = 0; j < 8; j++) {
        int q = q0 + qg + j * 8;
        OCb[((size_t)(b << 9) + q) * 256 + d * NH + h] = acc[j];
    }
}

// ---------------- MoE gating: softmax(1024) + top-2 (first-index tie-break) ----------------
__global__ void gating_kernel(const float* __restrict__ logits, float* __restrict__ raw,
                              float* __restrict__ g1, int* __restrict__ i1,
                              float* __restrict__ g2, int* __restrict__ i2) {
    int row = blockIdx.x;
    int tid = threadIdx.x;    // 256
    const float* p = logits + (size_t)row * EE;
    float lv[4];
#pragma unroll
    for (int j = 0; j < 4; j++) lv[j] = p[tid * 4 + j];
    __shared__ float sv[256];
    __shared__ int si[256];
    // phase 1: argmax
    float bv = lv[0]; int bi = tid * 4;
#pragma unroll
    for (int j = 1; j < 4; j++) if (lv[j] > bv) { bv = lv[j]; bi = tid * 4 + j; }
    sv[tid] = bv; si[tid] = bi; __syncthreads();
    for (int o = 128; o > 0; o >>= 1) {
        if (tid < o) {
            if (sv[tid + o] > sv[tid] || (sv[tid + o] == sv[tid] && si[tid + o] < si[tid])) {
                sv[tid] = sv[tid + o]; si[tid] = si[tid + o];
            }
        }
        __syncthreads();
    }
    float maxv = sv[0]; int maxi = si[0];
    __syncthreads();
    // phase 2: sum of exp
    float s = 0.f;
#pragma unroll
    for (int j = 0; j < 4; j++) s += expf(lv[j] - maxv);
    sv[tid] = s; __syncthreads();
    for (int o = 128; o > 0; o >>= 1) { if (tid < o) sv[tid] += sv[tid + o]; __syncthreads(); }
    float inv = 1.f / sv[0];
#pragma unroll
    for (int j = 0; j < 4; j++)
        raw[(size_t)row * EE + tid * 4 + j] = expf(lv[j] - maxv) * inv;
    __syncthreads();
    // phase 3: second max excluding maxi
    bv = -3.4e38f; bi = 0;
#pragma unroll
    for (int j = 0; j < 4; j++) {
        int e = tid * 4 + j;
        if (e != maxi && lv[j] > bv) { bv = lv[j]; bi = e; }
    }
    sv[tid] = bv; si[tid] = bi; __syncthreads();
    for (int o = 128; o > 0; o >>= 1) {
        if (tid < o) {
            if (sv[tid + o] > sv[tid] || (sv[tid + o] == sv[tid] && si[tid + o] < si[tid])) {
                sv[tid] = sv[tid + o]; si[tid] = si[tid + o];
            }
        }
        __syncthreads();
    }
    if (tid == 0) {
        float gate1v = inv;                       // exp(0) * inv
        float gate2v = expf(sv[0] - maxv) * inv;
        float denom = gate1v + gate2v + 1e-9f;
        g1[row] = gate1v / denom;
        i1[row] = maxi;
        g2[row] = gate2v / denom;
        i2[row] = si[0];
    }
}

// ---------------- per-(b,e) sum of raw over tokens (for aux loss) ----------------
__global__ void rawsum_kernel(const float* __restrict__ raw, float* __restrict__ rawsum) {
    int b = blockIdx.x >> 2;
    int chunk = blockIdx.x & 3;
    int e = chunk * 256 + threadIdx.x;
    const float* p = raw + (size_t)b * NTOK * EE + e;
    float s = 0.f;
    for (int n = 0; n < NTOK; n++) s += p[(size_t)n * EE];
    rawsum[b * EE + e] = s;
}

// ---------------- routing with capacity (sequential per batch) ----------------
__global__ void routing_kernel(const int* __restrict__ idx1, const float* __restrict__ gate1,
                               const int* __restrict__ idx2, const float* __restrict__ gate2,
                               int* __restrict__ slot_tok, float* __restrict__ slot_gate,
                               float* __restrict__ cnt1_out) {
    int b = blockIdx.x;
    int tid = threadIdx.x;
    __shared__ int cnt[EE];
    __shared__ int mcnt[EE];
    for (int e = tid; e < EE; e += 256) cnt[e] = 0;
    for (int i = tid; i < EE * CAPP; i += 256) {
        slot_tok[b * EE * CAPP + i] = -1;
        slot_gate[b * EE * CAPP + i] = 0.f;
    }
    __syncthreads();
    if (tid == 0) {
        for (int n = 0; n < NTOK; n++) {
            int e = idx1[b * NTOK + n];
            int pcur = cnt[e]++;
            if (pcur < CAPP) {
                slot_tok[(b * EE + e) * CAPP + pcur] = n;
                slot_gate[(b * EE + e) * CAPP + pcur] = gate1[b * NTOK + n];
            }
        }
    }
    __syncthreads();
    for (int e = tid; e < EE; e += 256) {
        cnt1_out[b * EE + e] = (float)cnt[e];
        mcnt[e] = cnt[e] < CAPP ? cnt[e] : CAPP;
        cnt[e] = 0;
    }
    __syncthreads();
    if (tid == 0) {
        for (int n = 0; n < NTOK; n++) {
            int e = idx2[b * NTOK + n];
            int pcur = mcnt[e] + cnt[e];
            cnt[e]++;
            if (pcur < CAPP) {
                slot_tok[(b * EE + e) * CAPP + pcur] = n;
                slot_gate[(b * EE + e) * CAPP + pcur] = gate2[b * NTOK + n];
            }
        }
    }
}

// ---------------- expert FFN: per-expert block, smem W1/W2, atomic scatter ----------------
__global__ void expert_kernel(const float* __restrict__ xm, const float* __restrict__ w1,
                              const float* __restrict__ w2,
                              const int* __restrict__ slot_tok, const float* __restrict__ slot_gate,
                              float* __restrict__ out) {
    int e = blockIdx.x;
    int tid = threadIdx.x;    // 256
    extern __shared__ float sw[];          // 512*32 floats = 64 KB
    __shared__ float hsh[32][33];
    __shared__ int stok[32];
    __shared__ float sgate[32];
    if (tid < 32) {
        int b = tid >> 2, c = tid & 3;
        stok[tid]  = slot_tok [(b * EE + e) * CAPP + c];
        sgate[tid] = slot_gate[(b * EE + e) * CAPP + c];
    }
    const float* w1e = w1 + (size_t)e * DTOK * HIDD;
#pragma unroll
    for (int i = 0; i < 64; i++) sw[tid + i * 256] = w1e[tid + i * 256];
    __syncthreads();
    int hid = tid & 31;
#pragma unroll
    for (int pass = 0; pass < 4; pass++) {
        int sidx = pass * 8 + (tid >> 5);
        int tok = stok[sidx];
        float acc = 0.f;
        if (tok >= 0) {
            const float* xr = xm + ((size_t)((sidx >> 2) * NTOK + tok)) * DTOK;
            for (int dd = 0; dd < DTOK; dd++) acc = fmaf(xr[dd], sw[dd * HIDD + hid], acc);
        }
        hsh[sidx][hid] = gelu_exact(acc);
    }
    __syncthreads();
    const float* w2e = w2 + (size_t)e * HIDD * DTOK;
#pragma unroll
    for (int i = 0; i < 64; i++) sw[tid + i * 256] = w2e[tid + i * 256];
    __syncthreads();
#pragma unroll
    for (int i = 0; i < 64; i++) {
        int idx = tid + i * 256;
        int sidx = idx >> 9;
        int dd = idx & 511;
        int tok = stok[sidx];
        float g = sgate[sidx];
        if (tok >= 0 && g != 0.f) {
            float acc = 0.f;
#pragma unroll
            for (int h2 = 0; h2 < HIDD; h2++) acc = fmaf(hsh[sidx][h2], sw[h2 * DTOK + dd], acc);
            atomicAdd(&out[((size_t)((sidx >> 2) * NTOK + tok)) * DTOK + dd], g * acc);
        }
    }
}

// ---------------- aux loss ----------------
__global__ void loss_kernel(const float* __restrict__ rawsum, const float* __restrict__ cnt1,
                            float* __restrict__ out_scalar) {
    __shared__ float red[256];
    int tid = threadIdx.x;
    float s = 0.f;
    for (int i = tid; i < BB * EE; i += 256) s += rawsum[i] * cnt1[i];
    red[tid] = s; __syncthreads();
    for (int o = 128; o > 0; o >>= 1) { if (tid < o) red[tid] += red[tid + o]; __syncthreads(); }
    if (tid == 0) out_scalar[0] = red[0] * 1.953125e-05f;   // 0.01*E^2/(B*E*n*n)
}

// ---------------- maxpool k=3 s=2 pad=1 ----------------
__global__ void maxpool_kernel(const float* __restrict__ yf, float* __restrict__ out) {
    int idx = blockIdx.x * 256 + threadIdx.x;   // 8*512*256
    int j = idx & 255;
    int o = (idx >> 8) & 511;
    int b = idx >> 17;
    const float* row = yf + ((size_t)(b * 512 + o)) * 512;
    int l = 2 * j;
    float m = row[l];
    if (l > 0) m = fmaxf(m, row[l - 1]);
    m = fmaxf(m, row[l + 1]);   // 2j+1 <= 511 always
    out[idx] = m;
}

// ---------------- host orchestration ----------------
extern "C" void kernel_launch(void* const* d_in, const int* in_sizes, int n_in,
                              void* d_out, int out_size) {
    const float* x        = (const float*)d_in[0];
    const float* emb      = (const float*)d_in[1];
    const float* rb1_g1s  = (const float*)d_in[2];
    const float* rb1_g1b  = (const float*)d_in[3];
    const float* rb1_c1w  = (const float*)d_in[4];
    const float* rb1_c1b  = (const float*)d_in[5];
    const float* rb1_g2s  = (const float*)d_in[6];
    const float* rb1_g2b  = (const float*)d_in[7];
    const float* rb1_c2w  = (const float*)d_in[8];
    const float* rb1_c2b  = (const float*)d_in[9];
    const float* rb2_g1s  = (const float*)d_in[10];
    const float* rb2_g1b  = (const float*)d_in[11];
    const float* rb2_c1w  = (const float*)d_in[12];
    const float* rb2_c1b  = (const float*)d_in[13];
    const float* rb2_g2s  = (const float*)d_in[14];
    const float* rb2_g2b  = (const float*)d_in[15];
    const float* rb2_c2w  = (const float*)d_in[16];
    const float* rb2_c2b  = (const float*)d_in[17];
    const float* attn_w1  = (const float*)d_in[18];
    const float* attn_b1  = (const float*)d_in[19];
    const float* attn_w2  = (const float*)d_in[20];
    const float* attn_b2  = (const float*)d_in[21];
    const float* moe_wg   = (const float*)d_in[22];
    const float* moe_w1   = (const float*)d_in[23];
    const float* moe_w2   = (const float*)d_in[24];
    const float* out_w    = (const float*)d_in[25];
    const float* out_b    = (const float*)d_in[26];
    float* out = (float*)d_out;

    float *px1, *ph, *pr, *pxa, *pxT, *pt, *pq, *pk, *pv, *ps, *poc, *plc, *pxb, *pxm;
    float *plog, *praw, *pg1, *pg2, *prs, *pc1, *psg, *pmo, *pyf;
    int *pi1, *pi2, *pst;
    cudaGetSymbolAddress((void**)&px1, g_x1);
    cudaGetSymbolAddress((void**)&ph,  g_h);
    cudaGetSymbolAddress((void**)&pr,  g_r);
    cudaGetSymbolAddress((void**)&pxa, g_xa);
    cudaGetSymbolAddress((void**)&pxT, g_xT);
    cudaGetSymbolAddress((void**)&pt,  g_t);
    cudaGetSymbolAddress((void**)&pq,  g_q);
    cudaGetSymbolAddress((void**)&pk,  g_k);
    cudaGetSymbolAddress((void**)&pv,  g_v);
    cudaGetSymbolAddress((void**)&ps,  g_s);
    cudaGetSymbolAddress((void**)&poc, g_oc);
    cudaGetSymbolAddress((void**)&plc, g_lc);
    cudaGetSymbolAddress((void**)&pxb, g_xb);
    cudaGetSymbolAddress((void**)&pxm, g_xm);
    cudaGetSymbolAddress((void**)&plog, g_logits);
    cudaGetSymbolAddress((void**)&praw, g_raw);
    cudaGetSymbolAddress((void**)&pg1, g_gate1);
    cudaGetSymbolAddress((void**)&pg2, g_gate2);
    cudaGetSymbolAddress((void**)&pi1, g_i1);
    cudaGetSymbolAddress((void**)&pi2, g_i2);
    cudaGetSymbolAddress((void**)&prs, g_rawsum);
    cudaGetSymbolAddress((void**)&pc1, g_cnt1);
    cudaGetSymbolAddress((void**)&pst, g_slot_tok);
    cudaGetSymbolAddress((void**)&psg, g_slot_gate);
    cudaGetSymbolAddress((void**)&pmo, g_moeout);
    cudaGetSymbolAddress((void**)&pyf, g_yfull);

    cudaFuncSetAttribute(expert_kernel, cudaFuncAttributeMaxDynamicSharedMemorySize, 65536);

    // ---- res block 1 ----
    gn_gelu_kernel<<<BB * NG, 256>>>(x, emb, rb1_g1s, rb1_g1b, px1, ph);
    conv3_kernel<<<dim3(64, 2), 256>>>(rb1_c1w, ph, rb1_c1b, nullptr, pr, 256);
    gn_gelu_kernel<<<BB * NG, 256>>>(pr, nullptr, rb1_g2s, rb1_g2b, nullptr, ph);
    conv3_kernel<<<dim3(64, 2), 256>>>(rb1_c2w, ph, rb1_c2b, px1, pxa, 256);

    // ---- attention ----
    transpose_kernel<<<dim3(16, 8, 8), dim3(32, 8)>>>(pxa, pxT, CC, LL);          // (B,C,L)->(B,L,C)
    sgemm_kernel<<<dim3(12, 32), 256>>>(pxT, attn_w1, attn_b1, pt, 4096, 768, 256);
    qkv_split_kernel<<<4096, 256>>>(pt, pq, pk, pv);
    attn_score_kernel<<<dim3(8, 8, 64), 256>>>(pq, pk, ps);
    softmax512_kernel<<<64 * 512, 128>>>(ps);
    attn_av_kernel<<<dim3(8, 64), 256>>>(ps, pv, poc);
    sgemm_kernel<<<dim3(4, 32), 256>>>(poc, attn_w2, attn_b2, plc, 4096, 256, 256);
    transpose_kernel<<<dim3(8, 16, 8), dim3(32, 8)>>>(plc, pxb, LL, CC);          // (B,L,C)->(B,C,L)

    // ---- res block 2 ----
    gn_gelu_kernel<<<BB * NG, 256>>>(pxb, emb, rb2_g1s, rb2_g1b, px1, ph);
    conv3_kernel<<<dim3(64, 2), 256>>>(rb2_c1w, ph, rb2_c1b, nullptr, pr, 256);
    gn_gelu_kernel<<<BB * NG, 256>>>(pr, nullptr, rb2_g2s, rb2_g2b, nullptr, ph);
    conv3_kernel<<<dim3(64, 2), 256>>>(rb2_c2w, ph, rb2_c2b, px1, pxm, 256);

    // ---- MoE ----
    sgemm_kernel<<<dim3(16, 16), 256>>>(pxm, moe_wg, nullptr, plog, 2048, 1024, 512);
    gating_kernel<<<2048, 256>>>(plog, praw, pg1, pi1, pg2, pi2);
    rawsum_kernel<<<32, 256>>>(praw, prs);
    routing_kernel<<<BB, 256>>>(pi1, pg1, pi2, pg2, pst, psg, pc1);
    cudaMemsetAsync(pmo, 0, sizeof(float) * BB * CC * LL);
    expert_kernel<<<EE, 256, 65536>>>(pxm, moe_w1, moe_w2, pst, psg, pmo);
    loss_kernel<<<1, 256>>>(prs, pc1, out + 2097152);

    // ---- output conv + maxpool ----
    conv3_kernel<<<dim3(64, 4), 256>>>(out_w, pmo, out_b, nullptr, pyf, 512);
    maxpool_kernel<<<4096, 256>>>(pyf, out);

    // second output: moe result x (B,C,L)
    cudaMemcpyAsync(out + 1048576, pmo, sizeof(float) * BB * CC * LL, cudaMemcpyDeviceToDevice);
}

// round 4
// speedup vs baseline: 1.2730x; 1.2730x over previous
#include <cuda_runtime.h>
#include <math.h>

// ---------------- problem constants ----------------
#define BB   8
#define CC   256
#define LL   512
#define NG   32      // groups
#define CPG  8       // channels per group
#define NH   8       // heads
#define DH   32      // head dim
#define EE   1024    // experts
#define HIDD 32
#define CAPP 4
#define NTOK 256     // tokens per batch for MoE (=C)
#define DTOK 512     // token dim for MoE (=L)

// ---------------- scratch (device globals; allocation-free) ----------------
__device__ float g_x1[BB*CC*LL];
__device__ float g_h [BB*CC*LL];
__device__ float g_r [BB*CC*LL];
__device__ float g_xa[BB*CC*LL];
__device__ float g_t [BB*LL*3*CC];
__device__ float g_q [BB*NH*LL*DH];
__device__ float g_k [BB*NH*LL*DH];
__device__ float g_v [BB*NH*LL*DH];
__device__ float g_s [(size_t)BB*NH*LL*LL];
__device__ float g_oc[BB*LL*CC];
__device__ float g_xb[BB*CC*LL];
__device__ float g_xm[BB*CC*LL];
__device__ float g_logits[BB*NTOK*EE];
__device__ float g_raw  [BB*NTOK*EE];
__device__ float g_gate1[BB*NTOK];
__device__ float g_gate2[BB*NTOK];
__device__ int   g_i1[BB*NTOK];
__device__ int   g_i2[BB*NTOK];
__device__ float g_rawsum[BB*EE];
__device__ float g_cnt1 [BB*EE];
__device__ int   g_slot_tok [BB*EE*CAPP];
__device__ float g_slot_gate[BB*EE*CAPP];
__device__ float g_moeout[BB*CC*LL];
__device__ float g_yfull[(size_t)BB*2*CC*LL];

__device__ __forceinline__ float gelu_exact(float v) {
    return 0.5f * v * (1.0f + erff(v * 0.7071067811865476f));
}

// ================= unified 64x64-tile GEMM, 128 threads, 8x4/thread =================
// A modes: AROW  A[m][k] row-major
//          AXT   A[m][k] = X[(b*CC + k)*LL + l], m = b*LL + l   (reads x transposed)
// B modes: BROW  B[k][n] row-major
//          BCONV B[k][n] = X[(b*CC + ic)*LL + (l+t-1)], k=(ic,t), n=(b,l), zero-pad
// C modes: CROW   C[m*N+n] (+bias[n] if bias)
//          CCONV  C[((b*M + m)<<9)+l], n=(b,l)  (+bias[m], +res same addr if res)
//          CTRANS C[((b*N + n)<<9)+l], m=(b,l)  (+bias[n] if bias)
#define AROW 0
#define AXT 1
#define BROW 0
#define BCONV 1
#define CROW 0
#define CCONV 1
#define CTRANS 2

template<int AM,int BM,int CM>
__global__ void gemm64(const float* __restrict__ A, const float* __restrict__ Bm,
                       const float* __restrict__ bias, const float* __restrict__ res,
                       float* __restrict__ Cm, int M, int N, int K) {
    __shared__ float As[16][64];
    __shared__ float Bs[16][64];
    int tid = threadIdx.x;          // 128
    int m0 = blockIdx.y * 64, n0 = blockIdx.x * 64;
    int tx = tid & 15, ty = tid >> 4;
    float ar[8], br[8];
    float acc[8][4] = {};
    int nk = K >> 4;

    auto loadA = [&](int k0) {
        if (AM == AROW) {
            int am = tid >> 1, ak = (tid & 1) * 8;
            const float* p = A + (size_t)(m0 + am) * K + k0 + ak;
            float4 v0 = *(const float4*)p;
            float4 v1 = *(const float4*)(p + 4);
            ar[0]=v0.x; ar[1]=v0.y; ar[2]=v0.z; ar[3]=v0.w;
            ar[4]=v1.x; ar[5]=v1.y; ar[6]=v1.z; ar[7]=v1.w;
        } else {
            int am = (tid & 15) * 4, ak = tid >> 4;      // ak 0..7, plus +8
            int mm = m0 + am; int bI = mm >> 9, l = mm & 511;
            const float* p = A + ((size_t)(bI * CC + k0 + ak) << 9) + l;
            float4 v0 = *(const float4*)p;
            float4 v1 = *(const float4*)(p + ((size_t)8 << 9));
            ar[0]=v0.x; ar[1]=v0.y; ar[2]=v0.z; ar[3]=v0.w;
            ar[4]=v1.x; ar[5]=v1.y; ar[6]=v1.z; ar[7]=v1.w;
        }
    };
    auto stsA = [&]() {
        if (AM == AROW) {
            int am = tid >> 1, ak = (tid & 1) * 8;
#pragma unroll
            for (int j = 0; j < 8; j++) As[ak + j][am] = ar[j];
        } else {
            int am = (tid & 15) * 4, ak = tid >> 4;
            *(float4*)&As[ak][am]     = make_float4(ar[0], ar[1], ar[2], ar[3]);
            *(float4*)&As[ak + 8][am] = make_float4(ar[4], ar[5], ar[6], ar[7]);
        }
    };
    auto loadB = [&](int k0) {
        int bk = tid >> 4, bn = (tid & 15) * 4;
        if (BM == BROW) {
            const float* p = Bm + (size_t)(k0 + bk) * N + n0 + bn;
            float4 v0 = *(const float4*)p;
            float4 v1 = *(const float4*)(p + (size_t)8 * N);
            br[0]=v0.x; br[1]=v0.y; br[2]=v0.z; br[3]=v0.w;
            br[4]=v1.x; br[5]=v1.y; br[6]=v1.z; br[7]=v1.w;
        } else {
            int nn = n0 + bn; int bI = nn >> 9, l = nn & 511;
#pragma unroll
            for (int jj = 0; jj < 2; jj++) {
                int kg = k0 + bk + jj * 8;
                int ic = kg / 3, t = kg - ic * 3;
                const float* base = Bm + ((size_t)(bI * CC + ic) << 9);
#pragma unroll
                for (int j = 0; j < 4; j++) {
                    int ll = l + j + t - 1;
                    br[jj * 4 + j] = ((unsigned)ll < 512u) ? base[ll] : 0.f;
                }
            }
        }
    };
    auto stsB = [&]() {
        int bk = tid >> 4, bn = (tid & 15) * 4;
        *(float4*)&Bs[bk][bn]     = make_float4(br[0], br[1], br[2], br[3]);
        *(float4*)&Bs[bk + 8][bn] = make_float4(br[4], br[5], br[6], br[7]);
    };

    loadA(0); loadB(0);
    for (int kt = 0; kt < nk; kt++) {
        __syncthreads();
        stsA(); stsB();
        __syncthreads();
        if (kt + 1 < nk) { loadA((kt + 1) << 4); loadB((kt + 1) << 4); }
#pragma unroll
        for (int kk = 0; kk < 16; kk++) {
            float4 a0 = *(const float4*)&As[kk][ty * 8];
            float4 a1 = *(const float4*)&As[kk][ty * 8 + 4];
            float4 bv = *(const float4*)&Bs[kk][tx * 4];
            float a[8] = {a0.x, a0.y, a0.z, a0.w, a1.x, a1.y, a1.z, a1.w};
            float bb[4] = {bv.x, bv.y, bv.z, bv.w};
#pragma unroll
            for (int i = 0; i < 8; i++)
#pragma unroll
                for (int j = 0; j < 4; j++) acc[i][j] = fmaf(a[i], bb[j], acc[i][j]);
        }
    }

    if (CM == CROW) {
        float bj[4] = {0.f, 0.f, 0.f, 0.f};
        if (bias) {
#pragma unroll
            for (int j = 0; j < 4; j++) bj[j] = bias[n0 + tx * 4 + j];
        }
#pragma unroll
        for (int i = 0; i < 8; i++) {
            int m = m0 + ty * 8 + i;
            *(float4*)&Cm[(size_t)m * N + n0 + tx * 4] =
                make_float4(acc[i][0] + bj[0], acc[i][1] + bj[1],
                            acc[i][2] + bj[2], acc[i][3] + bj[3]);
        }
    } else if (CM == CCONV) {
        int n = n0 + tx * 4; int bI = n >> 9, l = n & 511;
#pragma unroll
        for (int i = 0; i < 8; i++) {
            int o = m0 + ty * 8 + i;
            size_t oi = (((size_t)bI * M + o) << 9) + l;
            float bs = bias[o];
            float4 v = make_float4(acc[i][0] + bs, acc[i][1] + bs,
                                   acc[i][2] + bs, acc[i][3] + bs);
            if (res) {
                float4 r = *(const float4*)&res[oi];
                v.x += r.x; v.y += r.y; v.z += r.z; v.w += r.w;
            }
            *(float4*)&Cm[oi] = v;
        }
    } else {  // CTRANS
        int mbase = m0 + ty * 8; int bI = mbase >> 9, l = mbase & 511;
#pragma unroll
        for (int j = 0; j < 4; j++) {
            int n = n0 + tx * 4 + j;
            float bs = bias ? bias[n] : 0.f;
            size_t oi = (((size_t)bI * N + n) << 9) + l;
            *(float4*)&Cm[oi] = make_float4(acc[0][j] + bs, acc[1][j] + bs,
                                            acc[2][j] + bs, acc[3][j] + bs);
            *(float4*)&Cm[oi + 4] = make_float4(acc[4][j] + bs, acc[5][j] + bs,
                                                acc[6][j] + bs, acc[7][j] + bs);
        }
    }
}

// ---------------- GroupNorm (+optional emb add) + GELU, fused ----------------
__global__ void gn_gelu_kernel(const float* __restrict__ xin, const float* __restrict__ emb,
                               const float* __restrict__ scale, const float* __restrict__ bias,
                               float* __restrict__ x1_out, float* __restrict__ h_out) {
    int b = blockIdx.x >> 5;
    int g = blockIdx.x & 31;
    size_t base = ((size_t)b * CC + g * CPG) * LL;
    __shared__ float vals[CPG * LL];
    __shared__ float red[256];
    int tid = threadIdx.x;
    float s = 0.f, s2 = 0.f;
#pragma unroll
    for (int i = 0; i < 16; i++) {
        int j = tid + i * 256;
        float v = xin[base + j];
        if (emb) v += emb[base + j];
        vals[j] = v;
        s += v;
        s2 = fmaf(v, v, s2);
    }
    red[tid] = s; __syncthreads();
    for (int o = 128; o > 0; o >>= 1) { if (tid < o) red[tid] += red[tid + o]; __syncthreads(); }
    float mean = red[0] * (1.f / 4096.f);
    __syncthreads();
    red[tid] = s2; __syncthreads();
    for (int o = 128; o > 0; o >>= 1) { if (tid < o) red[tid] += red[tid + o]; __syncthreads(); }
    float var = red[0] * (1.f / 4096.f) - mean * mean;
    float rsig = rsqrtf(var + 1e-5f);
#pragma unroll
    for (int i = 0; i < 16; i++) {
        int j = tid + i * 256;
        int c = g * CPG + (j >> 9);
        float v = vals[j];
        if (x1_out) x1_out[base + j] = v;
        float nn = (v - mean) * rsig * scale[c] + bias[c];
        h_out[base + j] = gelu_exact(nn);
    }
}

// ---------------- qkv split: t(B,L,768) -> Q,K,V (B,H,L,DH) ----------------
__global__ void qkv_split_kernel(const float* __restrict__ t, float* __restrict__ Q,
                                 float* __restrict__ K, float* __restrict__ V) {
    int idx = blockIdx.x * 256 + threadIdx.x;
    int d = idx & 31;
    int l = (idx >> 5) & 511;
    int h = (idx >> 14) & 7;
    int b = idx >> 17;
    size_t base = ((size_t)(b * LL + l)) * 768 + (size_t)(d * NH + h) * 3;
    int o = ((b * NH + h) * LL + l) * DH + d;
    Q[o] = t[base];
    K[o] = t[base + 1];
    V[o] = t[base + 2];
}

// ---------------- scores S[bh,q,k] = Q.K / sqrt(DH) ----------------
__global__ void attn_score_kernel(const float* __restrict__ Q, const float* __restrict__ K,
                                  float* __restrict__ S) {
    int bh = blockIdx.z;
    int q0 = blockIdx.y * 64, k0 = blockIdx.x * 64;
    __shared__ float Qs[64][33];
    __shared__ float Ks[64][33];
    int tid = threadIdx.x;
#pragma unroll
    for (int i = 0; i < 8; i++) {
        int idx = tid + i * 256;
        int r = idx >> 5, d = idx & 31;
        Qs[r][d] = Q[((size_t)(bh << 9) + q0 + r) * 32 + d];
        Ks[r][d] = K[((size_t)(bh << 9) + k0 + r) * 32 + d];
    }
    __syncthreads();
    int tx = tid & 15, ty = tid >> 4;
    float acc[4][4] = {};
#pragma unroll
    for (int kk = 0; kk < 32; kk++) {
        float a[4], bq[4];
#pragma unroll
        for (int i = 0; i < 4; i++) a[i] = Qs[ty * 4 + i][kk];
#pragma unroll
        for (int j = 0; j < 4; j++) bq[j] = Ks[tx * 4 + j][kk];
#pragma unroll
        for (int i = 0; i < 4; i++)
#pragma unroll
            for (int j = 0; j < 4; j++) acc[i][j] = fmaf(a[i], bq[j], acc[i][j]);
    }
    const float sc = 0.17677669529663687f;
    size_t base = (size_t)bh << 18;
#pragma unroll
    for (int i = 0; i < 4; i++)
#pragma unroll
        for (int j = 0; j < 4; j++)
            S[base + (size_t)(q0 + ty * 4 + i) * 512 + k0 + tx * 4 + j] = acc[i][j] * sc;
}

// ---------------- softmax over rows of 512 ----------------
__global__ void softmax512_kernel(float* __restrict__ S) {
    size_t row = blockIdx.x;
    float* p = S + row * 512;
    int tid = threadIdx.x;       // 128
    __shared__ float red[128];
    float v[4];
#pragma unroll
    for (int i = 0; i < 4; i++) v[i] = p[tid + i * 128];
    float m = fmaxf(fmaxf(v[0], v[1]), fmaxf(v[2], v[3]));
    red[tid] = m; __syncthreads();
    for (int o = 64; o > 0; o >>= 1) { if (tid < o) red[tid] = fmaxf(red[tid], red[tid + o]); __syncthreads(); }
    m = red[0]; __syncthreads();
    float s = 0.f;
#pragma unroll
    for (int i = 0; i < 4; i++) { v[i] = expf(v[i] - m); s += v[i]; }
    red[tid] = s; __syncthreads();
    for (int o = 64; o > 0; o >>= 1) { if (tid < o) red[tid] += red[tid + o]; __syncthreads(); }
    float inv = 1.f / red[0];
#pragma unroll
    for (int i = 0; i < 4; i++) p[tid + i * 128] = v[i] * inv;
}

// ---------------- O = P @ V, write as oc[b,l, d*H + h] ----------------
__global__ void attn_av_kernel(const float* __restrict__ S, const float* __restrict__ V,
                               float* __restrict__ OCb) {
    int bh = blockIdx.y;
    int q0 = blockIdx.x * 64;
    int b = bh >> 3, h = bh & 7;
    __shared__ float Ps[64][65];
    __shared__ float Vs[64][32];
    int tid = threadIdx.x;
    int d = tid & 31, qg = tid >> 5;
    float acc[8] = {};
    for (int k0 = 0; k0 < 512; k0 += 64) {
#pragma unroll
        for (int i = 0; i < 16; i++) {
            int idx = tid + i * 256;
            int r = idx >> 6, c = idx & 63;
            Ps[r][c] = S[((size_t)bh << 18) + (size_t)(q0 + r) * 512 + k0 + c];
        }
#pragma unroll
        for (int i = 0; i < 8; i++) {
            int idx = tid + i * 256;
            int r = idx >> 5, c = idx & 31;
            Vs[r][c] = V[((size_t)(bh << 9) + k0 + r) * 32 + c];
        }
        __syncthreads();
#pragma unroll
        for (int kk = 0; kk < 64; kk++) {
            float vv = Vs[kk][d];
#pragma unroll
            for (int j = 0; j < 8; j++) acc[j] = fmaf(Ps[qg + j * 8][kk], vv, acc[j]);
        }
        __syncthreads();
    }
#pragma unroll
    for (int j = 0; j < 8; j++) {
        int q = q0 + qg + j * 8;
        OCb[((size_t)(b << 9) + q) * 256 + d * NH + h] = acc[j];
    }
}

// ---------------- MoE gating ----------------
__global__ void gating_kernel(const float* __restrict__ logits, float* __restrict__ raw,
                              float* __restrict__ g1, int* __restrict__ i1,
                              float* __restrict__ g2, int* __restrict__ i2) {
    int row = blockIdx.x;
    int tid = threadIdx.x;    // 256
    const float* p = logits + (size_t)row * EE;
    float lv[4];
#pragma unroll
    for (int j = 0; j < 4; j++) lv[j] = p[tid * 4 + j];
    __shared__ float sv[256];
    __shared__ int si[256];
    float bv = lv[0]; int bi = tid * 4;
#pragma unroll
    for (int j = 1; j < 4; j++) if (lv[j] > bv) { bv = lv[j]; bi = tid * 4 + j; }
    sv[tid] = bv; si[tid] = bi; __syncthreads();
    for (int o = 128; o > 0; o >>= 1) {
        if (tid < o) {
            if (sv[tid + o] > sv[tid] || (sv[tid + o] == sv[tid] && si[tid + o] < si[tid])) {
                sv[tid] = sv[tid + o]; si[tid] = si[tid + o];
            }
        }
        __syncthreads();
    }
    float maxv = sv[0]; int maxi = si[0];
    __syncthreads();
    float s = 0.f;
#pragma unroll
    for (int j = 0; j < 4; j++) s += expf(lv[j] - maxv);
    sv[tid] = s; __syncthreads();
    for (int o = 128; o > 0; o >>= 1) { if (tid < o) sv[tid] += sv[tid + o]; __syncthreads(); }
    float inv = 1.f / sv[0];
#pragma unroll
    for (int j = 0; j < 4; j++)
        raw[(size_t)row * EE + tid * 4 + j] = expf(lv[j] - maxv) * inv;
    __syncthreads();
    bv = -3.4e38f; bi = 0;
#pragma unroll
    for (int j = 0; j < 4; j++) {
        int e = tid * 4 + j;
        if (e != maxi && lv[j] > bv) { bv = lv[j]; bi = e; }
    }
    sv[tid] = bv; si[tid] = bi; __syncthreads();
    for (int o = 128; o > 0; o >>= 1) {
        if (tid < o) {
            if (sv[tid + o] > sv[tid] || (sv[tid + o] == sv[tid] && si[tid + o] < si[tid])) {
                sv[tid] = sv[tid + o]; si[tid] = si[tid + o];
            }
        }
        __syncthreads();
    }
    if (tid == 0) {
        float gate1v = inv;
        float gate2v = expf(sv[0] - maxv) * inv;
        float denom = gate1v + gate2v + 1e-9f;
        g1[row] = gate1v / denom;
        i1[row] = maxi;
        g2[row] = gate2v / denom;
        i2[row] = si[0];
    }
}

// ---------------- per-(b,e) sum of raw over tokens ----------------
__global__ void rawsum_kernel(const float* __restrict__ raw, float* __restrict__ rawsum) {
    int b = blockIdx.x >> 2;
    int chunk = blockIdx.x & 3;
    int e = chunk * 256 + threadIdx.x;
    const float* p = raw + (size_t)b * NTOK * EE + e;
    float s = 0.f;
    for (int n = 0; n < NTOK; n++) s += p[(size_t)n * EE];
    rawsum[b * EE + e] = s;
}

// ---------------- routing with capacity ----------------
__global__ void routing_kernel(const int* __restrict__ idx1, const float* __restrict__ gate1,
                               const int* __restrict__ idx2, const float* __restrict__ gate2,
                               int* __restrict__ slot_tok, float* __restrict__ slot_gate,
                               float* __restrict__ cnt1_out) {
    int b = blockIdx.x;
    int tid = threadIdx.x;
    __shared__ int cnt[EE];
    __shared__ int mcnt[EE];
    for (int e = tid; e < EE; e += 256) cnt[e] = 0;
    for (int i = tid; i < EE * CAPP; i += 256) {
        slot_tok[b * EE * CAPP + i] = -1;
        slot_gate[b * EE * CAPP + i] = 0.f;
    }
    __syncthreads();
    if (tid == 0) {
        for (int n = 0; n < NTOK; n++) {
            int e = idx1[b * NTOK + n];
            int pcur = cnt[e]++;
            if (pcur < CAPP) {
                slot_tok[(b * EE + e) * CAPP + pcur] = n;
                slot_gate[(b * EE + e) * CAPP + pcur] = gate1[b * NTOK + n];
            }
        }
    }
    __syncthreads();
    for (int e = tid; e < EE; e += 256) {
        cnt1_out[b * EE + e] = (float)cnt[e];
        mcnt[e] = cnt[e] < CAPP ? cnt[e] : CAPP;
        cnt[e] = 0;
    }
    __syncthreads();
    if (tid == 0) {
        for (int n = 0; n < NTOK; n++) {
            int e = idx2[b * NTOK + n];
            int pcur = mcnt[e] + cnt[e];
            cnt[e]++;
            if (pcur < CAPP) {
                slot_tok[(b * EE + e) * CAPP + pcur] = n;
                slot_gate[(b * EE + e) * CAPP + pcur] = gate2[b * NTOK + n];
            }
        }
    }
}

// ---------------- expert FFN ----------------
__global__ void expert_kernel(const float* __restrict__ xm, const float* __restrict__ w1,
                              const float* __restrict__ w2,
                              const int* __restrict__ slot_tok, const float* __restrict__ slot_gate,
                              float* __restrict__ out) {
    int e = blockIdx.x;
    int tid = threadIdx.x;    // 256
    extern __shared__ float sw[];          // 64 KB
    __shared__ float hsh[32][33];
    __shared__ int stok[32];
    __shared__ float sgate[32];
    __shared__ int s_any;
    if (tid < 32) {
        int b = tid >> 2, c = tid & 3;
        stok[tid]  = slot_tok [(b * EE + e) * CAPP + c];
        sgate[tid] = slot_gate[(b * EE + e) * CAPP + c];
    }
    if (tid == 0) s_any = 0;
    __syncthreads();
    if (tid == 0) {
        int a = 0;
        for (int i = 0; i < 32; i++) a |= (stok[i] >= 0);
        s_any = a;
    }
    __syncthreads();
    if (!s_any) return;
    const float* w1e = w1 + (size_t)e * DTOK * HIDD;
#pragma unroll
    for (int i = 0; i < 64; i++) sw[tid + i * 256] = w1e[tid + i * 256];
    __syncthreads();
    int hid = tid & 31;
#pragma unroll
    for (int pass = 0; pass < 4; pass++) {
        int sidx = pass * 8 + (tid >> 5);
        int tok = stok[sidx];
        float acc = 0.f;
        if (tok >= 0) {
            const float* xr = xm + ((size_t)((sidx >> 2) * NTOK + tok)) * DTOK;
            for (int dd = 0; dd < DTOK; dd++) acc = fmaf(xr[dd], sw[dd * HIDD + hid], acc);
        }
        hsh[sidx][hid] = gelu_exact(acc);
    }
    __syncthreads();
    const float* w2e = w2 + (size_t)e * HIDD * DTOK;
#pragma unroll
    for (int i = 0; i < 64; i++) sw[tid + i * 256] = w2e[tid + i * 256];
    __syncthreads();
#pragma unroll
    for (int i = 0; i < 64; i++) {
        int idx = tid + i * 256;
        int sidx = idx >> 9;
        int dd = idx & 511;
        int tok = stok[sidx];
        float g = sgate[sidx];
        if (tok >= 0 && g != 0.f) {
            float acc = 0.f;
#pragma unroll
            for (int h2 = 0; h2 < HIDD; h2++) acc = fmaf(hsh[sidx][h2], sw[h2 * DTOK + dd], acc);
            atomicAdd(&out[((size_t)((sidx >> 2) * NTOK + tok)) * DTOK + dd], g * acc);
        }
    }
}

// ---------------- aux loss ----------------
__global__ void loss_kernel(const float* __restrict__ rawsum, const float* __restrict__ cnt1,
                            float* __restrict__ out_scalar) {
    __shared__ float red[256];
    int tid = threadIdx.x;
    float s = 0.f;
    for (int i = tid; i < BB * EE; i += 256) s += rawsum[i] * cnt1[i];
    red[tid] = s; __syncthreads();
    for (int o = 128; o > 0; o >>= 1) { if (tid < o) red[tid] += red[tid + o]; __syncthreads(); }
    if (tid == 0) out_scalar[0] = red[0] * 1.953125e-05f;
}

// ---------------- maxpool k=3 s=2 pad=1 ----------------
__global__ void maxpool_kernel(const float* __restrict__ yf, float* __restrict__ out) {
    int idx = blockIdx.x * 256 + threadIdx.x;
    int j = idx & 255;
    int o = (idx >> 8) & 511;
    int b = idx >> 17;
    const float* row = yf + ((size_t)(b * 512 + o)) * 512;
    int l = 2 * j;
    float m = row[l];
    if (l > 0) m = fmaxf(m, row[l - 1]);
    m = fmaxf(m, row[l + 1]);
    out[idx] = m;
}

// ---------------- host orchestration ----------------
extern "C" void kernel_launch(void* const* d_in, const int* in_sizes, int n_in,
                              void* d_out, int out_size) {
    const float* x        = (const float*)d_in[0];
    const float* emb      = (const float*)d_in[1];
    const float* rb1_g1s  = (const float*)d_in[2];
    const float* rb1_g1b  = (const float*)d_in[3];
    const float* rb1_c1w  = (const float*)d_in[4];
    const float* rb1_c1b  = (const float*)d_in[5];
    const float* rb1_g2s  = (const float*)d_in[6];
    const float* rb1_g2b  = (const float*)d_in[7];
    const float* rb1_c2w  = (const float*)d_in[8];
    const float* rb1_c2b  = (const float*)d_in[9];
    const float* rb2_g1s  = (const float*)d_in[10];
    const float* rb2_g1b  = (const float*)d_in[11];
    const float* rb2_c1w  = (const float*)d_in[12];
    const float* rb2_c1b  = (const float*)d_in[13];
    const float* rb2_g2s  = (const float*)d_in[14];
    const float* rb2_g2b  = (const float*)d_in[15];
    const float* rb2_c2w  = (const float*)d_in[16];
    const float* rb2_c2b  = (const float*)d_in[17];
    const float* attn_w1  = (const float*)d_in[18];
    const float* attn_b1  = (const float*)d_in[19];
    const float* attn_w2  = (const float*)d_in[20];
    const float* attn_b2  = (const float*)d_in[21];
    const float* moe_wg   = (const float*)d_in[22];
    const float* moe_w1   = (const float*)d_in[23];
    const float* moe_w2   = (const float*)d_in[24];
    const float* out_w    = (const float*)d_in[25];
    const float* out_b    = (const float*)d_in[26];
    float* out = (float*)d_out;

    float *px1, *ph, *pr, *pxa, *pt, *pq, *pk, *pv, *ps, *poc, *pxb, *pxm;
    float *plog, *praw, *pg1, *pg2, *prs, *pc1, *psg, *pmo, *pyf;
    int *pi1, *pi2, *pst;
    cudaGetSymbolAddress((void**)&px1, g_x1);
    cudaGetSymbolAddress((void**)&ph,  g_h);
    cudaGetSymbolAddress((void**)&pr,  g_r);
    cudaGetSymbolAddress((void**)&pxa, g_xa);
    cudaGetSymbolAddress((void**)&pt,  g_t);
    cudaGetSymbolAddress((void**)&pq,  g_q);
    cudaGetSymbolAddress((void**)&pk,  g_k);
    cudaGetSymbolAddress((void**)&pv,  g_v);
    cudaGetSymbolAddress((void**)&ps,  g_s);
    cudaGetSymbolAddress((void**)&poc, g_oc);
    cudaGetSymbolAddress((void**)&pxb, g_xb);
    cudaGetSymbolAddress((void**)&pxm, g_xm);
    cudaGetSymbolAddress((void**)&plog, g_logits);
    cudaGetSymbolAddress((void**)&praw, g_raw);
    cudaGetSymbolAddress((void**)&pg1, g_gate1);
    cudaGetSymbolAddress((void**)&pg2, g_gate2);
    cudaGetSymbolAddress((void**)&pi1, g_i1);
    cudaGetSymbolAddress((void**)&pi2, g_i2);
    cudaGetSymbolAddress((void**)&prs, g_rawsum);
    cudaGetSymbolAddress((void**)&pc1, g_cnt1);
    cudaGetSymbolAddress((void**)&pst, g_slot_tok);
    cudaGetSymbolAddress((void**)&psg, g_slot_gate);
    cudaGetSymbolAddress((void**)&pmo, g_moeout);
    cudaGetSymbolAddress((void**)&pyf, g_yfull);

    cudaFuncSetAttribute(expert_kernel, cudaFuncAttributeMaxDynamicSharedMemorySize, 65536);

    // ---- res block 1 ----
    gn_gelu_kernel<<<BB * NG, 256>>>(x, emb, rb1_g1s, rb1_g1b, px1, ph);
    gemm64<AROW,BCONV,CCONV><<<dim3(64, 4), 128>>>(rb1_c1w, ph, rb1_c1b, nullptr, pr, 256, 4096, 768);
    gn_gelu_kernel<<<BB * NG, 256>>>(pr, nullptr, rb1_g2s, rb1_g2b, nullptr, ph);
    gemm64<AROW,BCONV,CCONV><<<dim3(64, 4), 128>>>(rb1_c2w, ph, rb1_c2b, px1, pxa, 256, 4096, 768);

    // ---- attention (transpose fused into GEMMs) ----
    gemm64<AXT,BROW,CROW><<<dim3(12, 64), 128>>>(pxa, attn_w1, attn_b1, nullptr, pt, 4096, 768, 256);
    qkv_split_kernel<<<4096, 256>>>(pt, pq, pk, pv);
    attn_score_kernel<<<dim3(8, 8, 64), 256>>>(pq, pk, ps);
    softmax512_kernel<<<64 * 512, 128>>>(ps);
    attn_av_kernel<<<dim3(8, 64), 256>>>(ps, pv, poc);
    gemm64<AROW,BROW,CTRANS><<<dim3(4, 64), 128>>>(poc, attn_w2, attn_b2, nullptr, pxb, 4096, 256, 256);

    // ---- res block 2 ----
    gn_gelu_kernel<<<BB * NG, 256>>>(pxb, emb, rb2_g1s, rb2_g1b, px1, ph);
    gemm64<AROW,BCONV,CCONV><<<dim3(64, 4), 128>>>(rb2_c1w, ph, rb2_c1b, nullptr, pr, 256, 4096, 768);
    gn_gelu_kernel<<<BB * NG, 256>>>(pr, nullptr, rb2_g2s, rb2_g2b, nullptr, ph);
    gemm64<AROW,BCONV,CCONV><<<dim3(64, 4), 128>>>(rb2_c2w, ph, rb2_c2b, px1, pxm, 256, 4096, 768);

    // ---- MoE ----
    gemm64<AROW,BROW,CROW><<<dim3(16, 32), 128>>>(pxm, moe_wg, nullptr, nullptr, plog, 2048, 1024, 512);
    gating_kernel<<<2048, 256>>>(plog, praw, pg1, pi1, pg2, pi2);
    rawsum_kernel<<<32, 256>>>(praw, prs);
    routing_kernel<<<BB, 256>>>(pi1, pg1, pi2, pg2, pst, psg, pc1);
    cudaMemsetAsync(pmo, 0, sizeof(float) * BB * CC * LL);
    expert_kernel<<<EE, 256, 65536>>>(pxm, moe_w1, moe_w2, pst, psg, pmo);
    loss_kernel<<<1, 256>>>(prs, pc1, out + 2097152);

    // ---- output conv + maxpool ----
    gemm64<AROW,BCONV,CCONV><<<dim3(64, 8), 128>>>(out_w, pmo, out_b, nullptr, pyf, 512, 4096, 768);
    maxpool_kernel<<<4096, 256>>>(pyf, out);

    // second output: moe result x (B,C,L)
    cudaMemcpyAsync(out + 1048576, pmo, sizeof(float) * BB * CC * LL, cudaMemcpyDeviceToDevice);
}